// round 8
// baseline (speedup 1.0000x reference)
#include <cuda_runtime.h>
#include <math.h>

#define HID   128
#define NG    20
#define EF    4
#define ZDIM  280      // 2*HID + NG + EF
#define NZDIM 256      // 2*HID
#define TE    32       // edges (or nodes) per CTA tile
#define NTHR  256
#define MAXN  50000

typedef unsigned long long u64;

// ---- static device scratch (no runtime allocation) ----
__device__ float g_mi[(size_t)MAXN * HID];
__device__ float g_dx[(size_t)MAXN * 3];

// k-interleaved packed weights: Wp[kp*128 + j] = (W[2kp][j], W[2kp+1][j])
#define WP_WE1  0
#define WP_WE2  (WP_WE1 + 140 * HID)   // ZDIM/2 = 140 kp rows
#define WP_WX1  (WP_WE2 + 64 * HID)
#define WP_WN1  (WP_WX1 + 64 * HID)
#define WP_WN2  (WP_WN1 + 128 * HID)   // NZDIM/2 = 128
#define WP_TOT  (WP_WN2 + 64 * HID)
__device__ __align__(16) u64 g_wp[WP_TOT];

__device__ __forceinline__ float siluf(float v) {
    return v * (1.0f / (1.0f + __expf(-v)));
}

// ---- packed f32x2 helpers ----
__device__ __forceinline__ void ffma2(u64& d, u64 a, u64 b) {
    asm("fma.rn.f32x2 %0, %1, %2, %0;" : "+l"(d) : "l"(a), "l"(b));
}
__device__ __forceinline__ void unpack2(u64 v, float& lo, float& hi) {
    asm("mov.b64 {%0, %1}, %2;" : "=f"(lo), "=f"(hi) : "l"(v));
}
__device__ __forceinline__ u64 packf2(float lo, float hi) {
    u64 r; asm("mov.b64 %0, {%1, %2};" : "=l"(r) : "f"(lo), "f"(hi)); return r;
}
// vector float4 reduction into global (no return)
__device__ __forceinline__ void red_add_v4(float* p, float a, float b, float c, float d) {
    asm volatile("red.global.add.v4.f32 [%0], {%1, %2, %3, %4};"
                 :: "l"(p), "f"(a), "f"(b), "f"(c), "f"(d) : "memory");
}

// Robust edge-index fetch: buffer may be int32 or little-endian int64.
__device__ __forceinline__ int load_idx(const int* __restrict__ ei32,
                                        long long pos, int is64, int N) {
    int v = is64 ? ei32[2 * pos] : ei32[pos];
    v = v < 0 ? 0 : v;
    return v >= N ? N - 1 : v;
}

// ----------------------------------------------------------------------------
// Weight pack kernel: interleave k-pairs.  W is [2*kps, 128] row-major.
// ----------------------------------------------------------------------------
__global__ void pack_kernel(const float* __restrict__ W, int kps, int base)
{
    int i = blockIdx.x * blockDim.x + threadIdx.x;
    if (i < kps * HID) {
        int kp = i >> 7, j = i & 127;
        g_wp[base + i] = packf2(W[(2 * kp) * HID + j], W[(2 * kp + 1) * HID + j]);
    }
}

// ----------------------------------------------------------------------------
// k-packed tile GEMM: out[4][4] = A[32][K] @ W[K][128] + bias  (this warp's
// 4 rows x 4 features).  FFMA2 pairs along k; accumulator = (even-k, odd-k),
// combined at the end (exact fp32 adds, reassociated).
// Per k-quad issues: 4 LDG.128 (Wp) + 4 LDS.128 (A) + 32 FFMA2.
// ----------------------------------------------------------------------------
template<int K, int AS>
__device__ __forceinline__ void gemm2k(const float* __restrict__ sA,
                                       const u64* __restrict__ Wp,
                                       const float* __restrict__ bias,
                                       float (&out)[4][4], int e0, int f0)
{
    u64 acc[4][4];
    #pragma unroll
    for (int i = 0; i < 4; i++)
        #pragma unroll
        for (int j = 0; j < 4; j++) acc[i][j] = 0ull;

    #pragma unroll 2
    for (int kq = 0; kq < K / 4; kq++) {
        ulonglong2 w0a = *(const ulonglong2*)&Wp[(2 * kq + 0) * HID + f0];
        ulonglong2 w0b = *(const ulonglong2*)&Wp[(2 * kq + 0) * HID + f0 + 2];
        ulonglong2 w1a = *(const ulonglong2*)&Wp[(2 * kq + 1) * HID + f0];
        ulonglong2 w1b = *(const ulonglong2*)&Wp[(2 * kq + 1) * HID + f0 + 2];
        #pragma unroll
        for (int i = 0; i < 4; i++) {
            // (a[4kq],a[4kq+1]) , (a[4kq+2],a[4kq+3]) — smem broadcast
            ulonglong2 ap = *(const ulonglong2*)&sA[(e0 + i) * AS + 4 * kq];
            ffma2(acc[i][0], ap.x, w0a.x);
            ffma2(acc[i][1], ap.x, w0a.y);
            ffma2(acc[i][2], ap.x, w0b.x);
            ffma2(acc[i][3], ap.x, w0b.y);
            ffma2(acc[i][0], ap.y, w1a.x);
            ffma2(acc[i][1], ap.y, w1a.y);
            ffma2(acc[i][2], ap.y, w1b.x);
            ffma2(acc[i][3], ap.y, w1b.y);
        }
    }
    float4 bv = *(const float4*)&bias[f0];
    const float* bp = (const float*)&bv;
    #pragma unroll
    for (int i = 0; i < 4; i++)
        #pragma unroll
        for (int j = 0; j < 4; j++) {
            float lo, hi; unpack2(acc[i][j], lo, hi);
            out[i][j] = lo + hi + bp[j];
        }
}

__device__ __forceinline__ void store_silu(float (&v)[4][4],
                                           float* __restrict__ sC, int e0, int f0)
{
    #pragma unroll
    for (int i = 0; i < 4; i++) {
        float4 o;
        o.x = siluf(v[i][0]); o.y = siluf(v[i][1]);
        o.z = siluf(v[i][2]); o.w = siluf(v[i][3]);
        *(float4*)&sC[(e0 + i) * HID + f0] = o;
    }
}

// ----------------------------------------------------------------------------
__global__ void zero_kernel()
{
    int i = blockIdx.x * blockDim.x + threadIdx.x;
    if (i < MAXN * HID / 4) ((float4*)g_mi)[i] = make_float4(0.f, 0.f, 0.f, 0.f);
    if (i < MAXN * 3)       g_dx[i] = 0.0f;
}

// ----------------------------------------------------------------------------
// Edge kernel: fused z -> silu -> silu -> {eij, silu -> xg} -> scatter.
// ----------------------------------------------------------------------------
__global__ void __launch_bounds__(NTHR, 2)
edge_kernel(const float* __restrict__ h, const float* __restrict__ x,
            const int* __restrict__ ei32, const float* __restrict__ eattr,
            const float* __restrict__ be1, const float* __restrict__ be2,
            const float* __restrict__ Winf, const float* __restrict__ binf,
            const float* __restrict__ bx1, const float* __restrict__ Wx2,
            int E, int N)
{
    extern __shared__ float smem[];
    float* Z = smem;                 // [TE][ZDIM]
    float* U = smem + TE * ZDIM;     // [TE][HID]
    float* M = smem;                 // alias Z (dead after GEMM1)
    float* V = U;                    // alias U (dead after GEMM2)

    __shared__ float sRel[TE][3];
    __shared__ float sD[TE];
    __shared__ float sE[TE];
    __shared__ float sXg[TE];
    __shared__ int   sDst[TE];

    const int tid  = threadIdx.x;
    const int lane = tid & 31;
    const int wy   = tid >> 5;
    const int e0   = wy * 4;
    const int f0   = lane * 4;
    const long long ebase = (long long)blockIdx.x * TE;

    const int is64 = (ei32[1] == 0 && ei32[3] == 0 &&
                      ei32[5] == 0 && ei32[7] == 0) ? 1 : 0;

    // ---- gather z tiles ----
    #pragma unroll
    for (int q = 0; q < 4; q++) {
        const int e = e0 + q;
        long long ge  = ebase + e;
        long long gec = (ge < E) ? ge : (long long)(E - 1);
        const int sidx = load_idx(ei32, gec, is64, N);                 // src
        const int didx = load_idx(ei32, (long long)E + gec, is64, N);  // dst

        *(float4*)&Z[e * ZDIM + f0]       = *(const float4*)&h[(long long)didx * HID + f0];
        *(float4*)&Z[e * ZDIM + HID + f0] = *(const float4*)&h[(long long)sidx * HID + f0];

        if (lane == 0) {
            float rx = x[didx * 3 + 0] - x[sidx * 3 + 0];
            float ry = x[didx * 3 + 1] - x[sidx * 3 + 1];
            float rz = x[didx * 3 + 2] - x[sidx * 3 + 2];
            float d  = sqrtf(rx * rx + ry * ry + rz * rz + 1e-8f);
            sRel[e][0] = rx; sRel[e][1] = ry; sRel[e][2] = rz;
            sD[e] = d; sDst[e] = didx;
        }
        __syncwarp();
        float d = sD[e];
        if (lane < NG) {
            float t = d - (float)lane * (10.0f / 19.0f);
            Z[e * ZDIM + 2 * HID + lane] = __expf(-1.805f * t * t);
        } else if (lane < NG + EF) {
            Z[e * ZDIM + 2 * HID + NG + (lane - NG)] = eattr[gec * EF + (lane - NG)];
        }
    }
    __syncthreads();

    // ---- GEMM1: U = silu(Z @ We1 + be1) ----
    {
        float v[4][4];
        gemm2k<ZDIM, ZDIM>(Z, g_wp + WP_WE1, be1, v, e0, f0);
        store_silu(v, U, e0, f0);
    }
    __syncthreads();

    // ---- GEMM2: M = silu(U @ We2 + be2)  (M overwrites Z region) ----
    {
        float v[4][4];
        gemm2k<HID, HID>(U, g_wp + WP_WE2, be2, v, e0, f0);
        store_silu(v, M, e0, f0);
    }
    __syncthreads();

    // ---- eij = sigmoid(M @ Winf + binf) ----
    #pragma unroll
    for (int q = 0; q < 4; q++) {
        const int e = e0 + q;
        float p = 0.0f;
        #pragma unroll
        for (int r = 0; r < 4; r++) {
            int f = lane + 32 * r;
            p = fmaf(M[e * HID + f], Winf[f], p);
        }
        #pragma unroll
        for (int off = 16; off > 0; off >>= 1)
            p += __shfl_xor_sync(0xffffffffu, p, off);
        if (lane == 0)
            sE[e] = 1.0f / (1.0f + __expf(-(p + binf[0])));
    }

    // ---- GEMM3: V = silu(M @ Wx1 + bx1)  (V overwrites U region) ----
    {
        float v[4][4];
        gemm2k<HID, HID>(M, g_wp + WP_WX1, bx1, v, e0, f0);
        store_silu(v, V, e0, f0);
    }
    __syncthreads();

    // ---- xg = tanh(V @ Wx2) ----
    #pragma unroll
    for (int q = 0; q < 4; q++) {
        const int e = e0 + q;
        float p = 0.0f;
        #pragma unroll
        for (int r = 0; r < 4; r++) {
            int f = lane + 32 * r;
            p = fmaf(V[e * HID + f], Wx2[f], p);
        }
        #pragma unroll
        for (int off = 16; off > 0; off >>= 1)
            p += __shfl_xor_sync(0xffffffffu, p, off);
        if (lane == 0)
            sXg[e] = tanhf(p);
    }
    __syncthreads();

    // ---- scatter: mi[dst] += m*eij ; dx[dst] += rel/(d+1)*xg ----
    #pragma unroll
    for (int i = 0; i < 4; i++) {
        const int e = e0 + i;
        if (ebase + e < E) {
            const float eij = sE[e];
            float* mip = &g_mi[(long long)sDst[e] * HID + f0];
            red_add_v4(mip,
                       M[e * HID + f0 + 0] * eij, M[e * HID + f0 + 1] * eij,
                       M[e * HID + f0 + 2] * eij, M[e * HID + f0 + 3] * eij);
        }
    }
    if (lane < 12) {
        const int q = lane / 3, c = lane % 3;
        const int e = e0 + q;
        if (ebase + e < E) {
            float val = sRel[e][c] / (sD[e] + 1.0f) * sXg[e];
            atomicAdd(&g_dx[sDst[e] * 3 + c], val);
        }
    }
}

// ----------------------------------------------------------------------------
// Node kernel.
// ----------------------------------------------------------------------------
__global__ void __launch_bounds__(NTHR, 2)
node_kernel(const float* __restrict__ h, const float* __restrict__ x,
            const float* __restrict__ mask,
            const float* __restrict__ bn1, const float* __restrict__ bn2,
            float* __restrict__ hout, float* __restrict__ xout, int N)
{
    extern __shared__ float smem[];
    float* NZ = smem;                  // [32][256]
    float* T  = smem + TE * NZDIM;     // [32][128]

    const int tid  = threadIdx.x;
    const int lane = tid & 31;
    const int wy   = tid >> 5;
    const int e0   = wy * 4;
    const int f0   = lane * 4;
    const long long nbase = (long long)blockIdx.x * TE;

    #pragma unroll
    for (int q = 0; q < 4; q++) {
        const int r = e0 + q;
        long long gn  = nbase + r;
        long long gnc = (gn < N) ? gn : (long long)(N - 1);
        *(float4*)&NZ[r * NZDIM + f0]       = *(const float4*)&g_mi[gnc * HID + f0];
        *(float4*)&NZ[r * NZDIM + HID + f0] = *(const float4*)&h[gnc * HID + f0];
    }
    __syncthreads();

    // T = silu(NZ @ Wn1 + bn1)
    {
        float v[4][4];
        gemm2k<NZDIM, NZDIM>(NZ, g_wp + WP_WN1, bn1, v, e0, f0);
        store_silu(v, T, e0, f0);
    }
    __syncthreads();

    // h_out = h + (T @ Wn2 + bn2)
    {
        float v[4][4];
        gemm2k<HID, HID>(T, g_wp + WP_WN2, bn2, v, e0, f0);
        #pragma unroll
        for (int i = 0; i < 4; i++) {
            const int r = e0 + i;
            long long gn = nbase + r;
            if (gn < N) {
                float4 o;
                o.x = v[i][0] + NZ[r * NZDIM + HID + f0 + 0];
                o.y = v[i][1] + NZ[r * NZDIM + HID + f0 + 1];
                o.z = v[i][2] + NZ[r * NZDIM + HID + f0 + 2];
                o.w = v[i][3] + NZ[r * NZDIM + HID + f0 + 3];
                *(float4*)&hout[gn * HID + f0] = o;
            }
        }
    }

    // x_out = x + dx * mask
    if (lane < 12) {
        const int q = lane / 3, c = lane % 3;
        long long gn = nbase + e0 + q;
        if (gn < N)
            xout[gn * 3 + c] = x[gn * 3 + c] + g_dx[gn * 3 + c] * mask[gn];
    }
}

// ----------------------------------------------------------------------------
extern "C" void kernel_launch(void* const* d_in, const int* in_sizes, int n_in,
                              void* d_out, int out_size)
{
    const float* h     = (const float*)d_in[0];
    const float* x     = (const float*)d_in[1];
    const int*   ei32  = (const int*)d_in[2];     // int32 OR int64 (device-probed)
    const float* mask  = (const float*)d_in[3];
    const float* eattr = (const float*)d_in[4];
    const float* We1   = (const float*)d_in[5];
    const float* be1   = (const float*)d_in[6];
    const float* We2   = (const float*)d_in[7];
    const float* be2   = (const float*)d_in[8];
    const float* Winf  = (const float*)d_in[9];
    const float* binf  = (const float*)d_in[10];
    const float* Wx1   = (const float*)d_in[11];
    const float* bx1   = (const float*)d_in[12];
    const float* Wx2   = (const float*)d_in[13];
    const float* Wn1   = (const float*)d_in[14];
    const float* bn1   = (const float*)d_in[15];
    const float* Wn2   = (const float*)d_in[16];
    const float* bn2   = (const float*)d_in[17];

    const int N = in_sizes[0] / HID;
    const int E = in_sizes[2] / 2;

    float* hout = (float*)d_out;
    float* xout = hout + (size_t)N * HID;

    const int edge_smem = (TE * ZDIM + TE * HID) * (int)sizeof(float);   // 52224 B
    const int node_smem = (TE * NZDIM + TE * HID) * (int)sizeof(float);  // 49152 B
    cudaFuncSetAttribute(edge_kernel, cudaFuncAttributeMaxDynamicSharedMemorySize, edge_smem);
    cudaFuncSetAttribute(node_kernel, cudaFuncAttributeMaxDynamicSharedMemorySize, node_smem);

    // weight prepack (k-interleaved pairs) — deterministic, runs every launch
    pack_kernel<<<(140 * HID + NTHR - 1) / NTHR, NTHR>>>(We1, 140, WP_WE1);
    pack_kernel<<<( 64 * HID + NTHR - 1) / NTHR, NTHR>>>(We2,  64, WP_WE2);
    pack_kernel<<<( 64 * HID + NTHR - 1) / NTHR, NTHR>>>(Wx1,  64, WP_WX1);
    pack_kernel<<<(128 * HID + NTHR - 1) / NTHR, NTHR>>>(Wn1, 128, WP_WN1);
    pack_kernel<<<( 64 * HID + NTHR - 1) / NTHR, NTHR>>>(Wn2,  64, WP_WN2);

    zero_kernel<<<(MAXN * HID + NTHR - 1) / NTHR, NTHR>>>();
    edge_kernel<<<(E + TE - 1) / TE, NTHR, edge_smem>>>(
        h, x, ei32, eattr, be1, be2, Winf, binf, bx1, Wx2, E, N);
    node_kernel<<<(N + TE - 1) / TE, NTHR, node_smem>>>(
        h, x, mask, bn1, bn2, hout, xout, N);
}

// round 9
// speedup vs baseline: 1.3102x; 1.3102x over previous
#include <cuda_runtime.h>
#include <math.h>

#define HID   128
#define NG    20
#define EF    4
#define ZDIM  280      // 2*HID + NG + EF
#define NZDIM 256      // 2*HID
#define TE    32       // edges (or nodes) per CTA tile
#define NTHR  256
#define MAXN  50000

typedef unsigned long long u64;

// ---- static device scratch (no runtime allocation) ----
__device__ float g_mi[(size_t)MAXN * HID];
__device__ float g_dx[(size_t)MAXN * 3];

// k-interleaved packed weights: Wp[kp*128 + j] = (W[2kp][j], W[2kp+1][j])
#define WP_WE1  0
#define WP_WE2  (WP_WE1 + 140 * HID)   // ZDIM/2 = 140 kp rows
#define WP_WX1  (WP_WE2 + 64 * HID)
#define WP_WN1  (WP_WX1 + 64 * HID)
#define WP_WN2  (WP_WN1 + 128 * HID)   // NZDIM/2 = 128
#define WP_TOT  (WP_WN2 + 64 * HID)
__device__ __align__(16) u64 g_wp[WP_TOT];

__device__ __forceinline__ float siluf(float v) {
    return v * (1.0f / (1.0f + __expf(-v)));
}

// ---- packed f32x2 helpers ----
__device__ __forceinline__ void ffma2(u64& d, u64 a, u64 b) {
    asm("fma.rn.f32x2 %0, %1, %2, %0;" : "+l"(d) : "l"(a), "l"(b));
}
__device__ __forceinline__ void unpack2(u64 v, float& lo, float& hi) {
    asm("mov.b64 {%0, %1}, %2;" : "=f"(lo), "=f"(hi) : "l"(v));
}
__device__ __forceinline__ u64 packf2(float lo, float hi) {
    u64 r; asm("mov.b64 %0, {%1, %2};" : "=l"(r) : "f"(lo), "f"(hi)); return r;
}
// vector float2 reduction into global (no return)
__device__ __forceinline__ void red_add_v2(float* p, float a, float b) {
    asm volatile("red.global.add.v2.f32 [%0], {%1, %2};"
                 :: "l"(p), "f"(a), "f"(b) : "memory");
}

// Robust edge-index fetch: buffer may be int32 or little-endian int64.
__device__ __forceinline__ int load_idx(const int* __restrict__ ei32,
                                        long long pos, int is64, int N) {
    int v = is64 ? ei32[2 * pos] : ei32[pos];
    v = v < 0 ? 0 : v;
    return v >= N ? N - 1 : v;
}

// ----------------------------------------------------------------------------
// Weight pack kernel: interleave k-pairs.  W is [2*kps, 128] row-major.
// ----------------------------------------------------------------------------
__global__ void pack_kernel(const float* __restrict__ W, int kps, int base)
{
    int i = blockIdx.x * blockDim.x + threadIdx.x;
    if (i < kps * HID) {
        int kp = i >> 7, j = i & 127;
        g_wp[base + i] = packf2(W[(2 * kp) * HID + j], W[(2 * kp + 1) * HID + j]);
    }
}

// ----------------------------------------------------------------------------
// k-packed tile GEMM with coalesced W loads.
// Lane owns output features {2l, 2l+1, 64+2l, 64+2l+1}  (fa = 2*lane, fb = 64+2*lane)
//  -> each W row-pair read as two ulonglong2 at 16B/lane stride: fully coalesced.
// FFMA2 pairs along k; acc = (even-k sum, odd-k sum), combined at the end
// (exact fp32 adds, reassociated). Per k-quad: 4 LDG.128 + 4 LDS.128 + 32 FFMA2.
// ----------------------------------------------------------------------------
template<int K, int AS>
__device__ __forceinline__ void gemm2k(const float* __restrict__ sA,
                                       const u64* __restrict__ Wp,
                                       const float* __restrict__ bias,
                                       float (&out)[4][4], int e0, int fa, int fb)
{
    u64 acc[4][4];
    #pragma unroll
    for (int i = 0; i < 4; i++)
        #pragma unroll
        for (int j = 0; j < 4; j++) acc[i][j] = 0ull;

    #pragma unroll 2
    for (int kq = 0; kq < K / 4; kq++) {
        ulonglong2 w0lo = *(const ulonglong2*)&Wp[(2 * kq + 0) * HID + fa];
        ulonglong2 w0hi = *(const ulonglong2*)&Wp[(2 * kq + 0) * HID + fb];
        ulonglong2 w1lo = *(const ulonglong2*)&Wp[(2 * kq + 1) * HID + fa];
        ulonglong2 w1hi = *(const ulonglong2*)&Wp[(2 * kq + 1) * HID + fb];
        #pragma unroll
        for (int i = 0; i < 4; i++) {
            // (a[4kq],a[4kq+1]) , (a[4kq+2],a[4kq+3]) — warp-broadcast from smem
            ulonglong2 ap = *(const ulonglong2*)&sA[(e0 + i) * AS + 4 * kq];
            ffma2(acc[i][0], ap.x, w0lo.x);
            ffma2(acc[i][1], ap.x, w0lo.y);
            ffma2(acc[i][2], ap.x, w0hi.x);
            ffma2(acc[i][3], ap.x, w0hi.y);
            ffma2(acc[i][0], ap.y, w1lo.x);
            ffma2(acc[i][1], ap.y, w1lo.y);
            ffma2(acc[i][2], ap.y, w1hi.x);
            ffma2(acc[i][3], ap.y, w1hi.y);
        }
    }
    float2 ba = *(const float2*)&bias[fa];
    float2 bb = *(const float2*)&bias[fb];
    #pragma unroll
    for (int i = 0; i < 4; i++) {
        float lo, hi;
        unpack2(acc[i][0], lo, hi); out[i][0] = lo + hi + ba.x;
        unpack2(acc[i][1], lo, hi); out[i][1] = lo + hi + ba.y;
        unpack2(acc[i][2], lo, hi); out[i][2] = lo + hi + bb.x;
        unpack2(acc[i][3], lo, hi); out[i][3] = lo + hi + bb.y;
    }
}

__device__ __forceinline__ void store_silu(float (&v)[4][4],
                                           float* __restrict__ sC,
                                           int e0, int fa, int fb)
{
    #pragma unroll
    for (int i = 0; i < 4; i++) {
        *(float2*)&sC[(e0 + i) * HID + fa] = make_float2(siluf(v[i][0]), siluf(v[i][1]));
        *(float2*)&sC[(e0 + i) * HID + fb] = make_float2(siluf(v[i][2]), siluf(v[i][3]));
    }
}

// ----------------------------------------------------------------------------
__global__ void zero_kernel()
{
    int i = blockIdx.x * blockDim.x + threadIdx.x;
    if (i < MAXN * HID / 4) ((float4*)g_mi)[i] = make_float4(0.f, 0.f, 0.f, 0.f);
    if (i < MAXN * 3)       g_dx[i] = 0.0f;
}

// ----------------------------------------------------------------------------
// Edge kernel: fused z -> silu -> silu -> {eij, silu -> xg} -> scatter.
// ----------------------------------------------------------------------------
__global__ void __launch_bounds__(NTHR, 2)
edge_kernel(const float* __restrict__ h, const float* __restrict__ x,
            const int* __restrict__ ei32, const float* __restrict__ eattr,
            const float* __restrict__ be1, const float* __restrict__ be2,
            const float* __restrict__ Winf, const float* __restrict__ binf,
            const float* __restrict__ bx1, const float* __restrict__ Wx2,
            int E, int N)
{
    extern __shared__ float smem[];
    float* Z = smem;                 // [TE][ZDIM]
    float* U = smem + TE * ZDIM;     // [TE][HID]
    float* M = smem;                 // alias Z (dead after GEMM1)
    float* V = U;                    // alias U (dead after GEMM2)

    __shared__ float sRel[TE][3];
    __shared__ float sD[TE];
    __shared__ float sE[TE];
    __shared__ float sXg[TE];
    __shared__ int   sDst[TE];

    const int tid  = threadIdx.x;
    const int lane = tid & 31;
    const int wy   = tid >> 5;
    const int e0   = wy * 4;
    const int f0   = lane * 4;        // gather-phase mapping only
    const int fa   = 2 * lane;        // GEMM features {fa, fa+1}
    const int fb   = 64 + 2 * lane;   //               {fb, fb+1}
    const long long ebase = (long long)blockIdx.x * TE;

    const int is64 = (ei32[1] == 0 && ei32[3] == 0 &&
                      ei32[5] == 0 && ei32[7] == 0) ? 1 : 0;

    // ---- gather z tiles ----
    #pragma unroll
    for (int q = 0; q < 4; q++) {
        const int e = e0 + q;
        long long ge  = ebase + e;
        long long gec = (ge < E) ? ge : (long long)(E - 1);
        const int sidx = load_idx(ei32, gec, is64, N);                 // src
        const int didx = load_idx(ei32, (long long)E + gec, is64, N);  // dst

        *(float4*)&Z[e * ZDIM + f0]       = *(const float4*)&h[(long long)didx * HID + f0];
        *(float4*)&Z[e * ZDIM + HID + f0] = *(const float4*)&h[(long long)sidx * HID + f0];

        if (lane == 0) {
            float rx = x[didx * 3 + 0] - x[sidx * 3 + 0];
            float ry = x[didx * 3 + 1] - x[sidx * 3 + 1];
            float rz = x[didx * 3 + 2] - x[sidx * 3 + 2];
            float d  = sqrtf(rx * rx + ry * ry + rz * rz + 1e-8f);
            sRel[e][0] = rx; sRel[e][1] = ry; sRel[e][2] = rz;
            sD[e] = d; sDst[e] = didx;
        }
        __syncwarp();
        float d = sD[e];
        if (lane < NG) {
            float t = d - (float)lane * (10.0f / 19.0f);
            Z[e * ZDIM + 2 * HID + lane] = __expf(-1.805f * t * t);
        } else if (lane < NG + EF) {
            Z[e * ZDIM + 2 * HID + NG + (lane - NG)] = eattr[gec * EF + (lane - NG)];
        }
    }
    __syncthreads();

    // ---- GEMM1: U = silu(Z @ We1 + be1) ----
    {
        float v[4][4];
        gemm2k<ZDIM, ZDIM>(Z, g_wp + WP_WE1, be1, v, e0, fa, fb);
        store_silu(v, U, e0, fa, fb);
    }
    __syncthreads();

    // ---- GEMM2: M = silu(U @ We2 + be2)  (M overwrites Z region) ----
    {
        float v[4][4];
        gemm2k<HID, HID>(U, g_wp + WP_WE2, be2, v, e0, fa, fb);
        store_silu(v, M, e0, fa, fb);
    }
    __syncthreads();

    // ---- eij = sigmoid(M @ Winf + binf) ----
    #pragma unroll
    for (int q = 0; q < 4; q++) {
        const int e = e0 + q;
        float p = 0.0f;
        #pragma unroll
        for (int r = 0; r < 4; r++) {
            int f = lane + 32 * r;
            p = fmaf(M[e * HID + f], Winf[f], p);
        }
        #pragma unroll
        for (int off = 16; off > 0; off >>= 1)
            p += __shfl_xor_sync(0xffffffffu, p, off);
        if (lane == 0)
            sE[e] = 1.0f / (1.0f + __expf(-(p + binf[0])));
    }

    // ---- GEMM3: V = silu(M @ Wx1 + bx1)  (V overwrites U region) ----
    {
        float v[4][4];
        gemm2k<HID, HID>(M, g_wp + WP_WX1, bx1, v, e0, fa, fb);
        store_silu(v, V, e0, fa, fb);
    }
    __syncthreads();

    // ---- xg = tanh(V @ Wx2) ----
    #pragma unroll
    for (int q = 0; q < 4; q++) {
        const int e = e0 + q;
        float p = 0.0f;
        #pragma unroll
        for (int r = 0; r < 4; r++) {
            int f = lane + 32 * r;
            p = fmaf(V[e * HID + f], Wx2[f], p);
        }
        #pragma unroll
        for (int off = 16; off > 0; off >>= 1)
            p += __shfl_xor_sync(0xffffffffu, p, off);
        if (lane == 0)
            sXg[e] = tanhf(p);
    }
    __syncthreads();

    // ---- scatter: mi[dst] += m*eij ; dx[dst] += rel/(d+1)*xg ----
    #pragma unroll
    for (int i = 0; i < 4; i++) {
        const int e = e0 + i;
        if (ebase + e < E) {
            const float eij = sE[e];
            float* mip = &g_mi[(long long)sDst[e] * HID];
            red_add_v2(mip + fa, M[e * HID + fa] * eij, M[e * HID + fa + 1] * eij);
            red_add_v2(mip + fb, M[e * HID + fb] * eij, M[e * HID + fb + 1] * eij);
        }
    }
    if (lane < 12) {
        const int q = lane / 3, c = lane % 3;
        const int e = e0 + q;
        if (ebase + e < E) {
            float val = sRel[e][c] / (sD[e] + 1.0f) * sXg[e];
            atomicAdd(&g_dx[sDst[e] * 3 + c], val);
        }
    }
}

// ----------------------------------------------------------------------------
// Node kernel.
// ----------------------------------------------------------------------------
__global__ void __launch_bounds__(NTHR, 2)
node_kernel(const float* __restrict__ h, const float* __restrict__ x,
            const float* __restrict__ mask,
            const float* __restrict__ bn1, const float* __restrict__ bn2,
            float* __restrict__ hout, float* __restrict__ xout, int N)
{
    extern __shared__ float smem[];
    float* NZ = smem;                  // [32][256]
    float* T  = smem + TE * NZDIM;     // [32][128]

    const int tid  = threadIdx.x;
    const int lane = tid & 31;
    const int wy   = tid >> 5;
    const int e0   = wy * 4;
    const int f0   = lane * 4;
    const int fa   = 2 * lane;
    const int fb   = 64 + 2 * lane;
    const long long nbase = (long long)blockIdx.x * TE;

    #pragma unroll
    for (int q = 0; q < 4; q++) {
        const int r = e0 + q;
        long long gn  = nbase + r;
        long long gnc = (gn < N) ? gn : (long long)(N - 1);
        *(float4*)&NZ[r * NZDIM + f0]       = *(const float4*)&g_mi[gnc * HID + f0];
        *(float4*)&NZ[r * NZDIM + HID + f0] = *(const float4*)&h[gnc * HID + f0];
    }
    __syncthreads();

    // T = silu(NZ @ Wn1 + bn1)
    {
        float v[4][4];
        gemm2k<NZDIM, NZDIM>(NZ, g_wp + WP_WN1, bn1, v, e0, fa, fb);
        store_silu(v, T, e0, fa, fb);
    }
    __syncthreads();

    // h_out = h + (T @ Wn2 + bn2)
    {
        float v[4][4];
        gemm2k<HID, HID>(T, g_wp + WP_WN2, bn2, v, e0, fa, fb);
        #pragma unroll
        for (int i = 0; i < 4; i++) {
            const int r = e0 + i;
            long long gn = nbase + r;
            if (gn < N) {
                float2 oa, ob;
                oa.x = v[i][0] + NZ[r * NZDIM + HID + fa];
                oa.y = v[i][1] + NZ[r * NZDIM + HID + fa + 1];
                ob.x = v[i][2] + NZ[r * NZDIM + HID + fb];
                ob.y = v[i][3] + NZ[r * NZDIM + HID + fb + 1];
                *(float2*)&hout[gn * HID + fa] = oa;
                *(float2*)&hout[gn * HID + fb] = ob;
            }
        }
    }

    // x_out = x + dx * mask
    if (lane < 12) {
        const int q = lane / 3, c = lane % 3;
        long long gn = nbase + e0 + q;
        if (gn < N)
            xout[gn * 3 + c] = x[gn * 3 + c] + g_dx[gn * 3 + c] * mask[gn];
    }
}

// ----------------------------------------------------------------------------
extern "C" void kernel_launch(void* const* d_in, const int* in_sizes, int n_in,
                              void* d_out, int out_size)
{
    const float* h     = (const float*)d_in[0];
    const float* x     = (const float*)d_in[1];
    const int*   ei32  = (const int*)d_in[2];     // int32 OR int64 (device-probed)
    const float* mask  = (const float*)d_in[3];
    const float* eattr = (const float*)d_in[4];
    const float* We1   = (const float*)d_in[5];
    const float* be1   = (const float*)d_in[6];
    const float* We2   = (const float*)d_in[7];
    const float* be2   = (const float*)d_in[8];
    const float* Winf  = (const float*)d_in[9];
    const float* binf  = (const float*)d_in[10];
    const float* Wx1   = (const float*)d_in[11];
    const float* bx1   = (const float*)d_in[12];
    const float* Wx2   = (const float*)d_in[13];
    const float* Wn1   = (const float*)d_in[14];
    const float* bn1   = (const float*)d_in[15];
    const float* Wn2   = (const float*)d_in[16];
    const float* bn2   = (const float*)d_in[17];

    const int N = in_sizes[0] / HID;
    const int E = in_sizes[2] / 2;

    float* hout = (float*)d_out;
    float* xout = hout + (size_t)N * HID;

    const int edge_smem = (TE * ZDIM + TE * HID) * (int)sizeof(float);   // 52224 B
    const int node_smem = (TE * NZDIM + TE * HID) * (int)sizeof(float);  // 49152 B
    cudaFuncSetAttribute(edge_kernel, cudaFuncAttributeMaxDynamicSharedMemorySize, edge_smem);
    cudaFuncSetAttribute(node_kernel, cudaFuncAttributeMaxDynamicSharedMemorySize, node_smem);

    // weight prepack (k-interleaved pairs) — deterministic, runs every launch
    pack_kernel<<<(140 * HID + NTHR - 1) / NTHR, NTHR>>>(We1, 140, WP_WE1);
    pack_kernel<<<( 64 * HID + NTHR - 1) / NTHR, NTHR>>>(We2,  64, WP_WE2);
    pack_kernel<<<( 64 * HID + NTHR - 1) / NTHR, NTHR>>>(Wx1,  64, WP_WX1);
    pack_kernel<<<(128 * HID + NTHR - 1) / NTHR, NTHR>>>(Wn1, 128, WP_WN1);
    pack_kernel<<<( 64 * HID + NTHR - 1) / NTHR, NTHR>>>(Wn2,  64, WP_WN2);

    zero_kernel<<<(MAXN * HID + NTHR - 1) / NTHR, NTHR>>>();
    edge_kernel<<<(E + TE - 1) / TE, NTHR, edge_smem>>>(
        h, x, ei32, eattr, be1, be2, Winf, binf, bx1, Wx2, E, N);
    node_kernel<<<(N + TE - 1) / TE, NTHR, node_smem>>>(
        h, x, mask, bn1, bn2, hout, xout, N);
}